// round 5
// baseline (speedup 1.0000x reference)
#include <cuda_runtime.h>
#include <math.h>

#define TT   1460
#define GG   5000
#define TS   30              // timesteps per smem tile in scan kernel
#define NT   49              // ceil(1460/30)
#define ROWF 96              // 32 cells * 3 floats per timestep row
#define CH   15              // UH length
#define NSL  14              // conv t-slices (14 * 105 = 1470 >= 1460)
#define SLEN 105             // steps per conv slice (7 * 15)

// 58.4 MB scratch: (ht0, ht1) per (t, g)
__device__ float2 g_scratch[(size_t)TT * GG];

// ---- packed f32x2 + approx transcendental helpers -----------------------------
#define PACK2(d, lo, hi)   asm("mov.b64 %0, {%1, %2};" : "=l"(d) : "f"(lo), "f"(hi))
#define UNPACK2(lo, hi, d) asm("mov.b64 {%0, %1}, %2;" : "=f"(lo), "=f"(hi) : "l"(d))
#define FMA2(d, a, b, c)   asm("fma.rn.f32x2 %0, %1, %2, %3;" : "=l"(d) : "l"(a), "l"(b), "l"(c))

__device__ __forceinline__ float lg2a(float x) { float r; asm("lg2.approx.f32 %0, %1;" : "=f"(r) : "f"(x)); return r; }
__device__ __forceinline__ float ex2a(float x) { float r; asm("ex2.approx.f32 %0, %1;" : "=f"(r) : "f"(x)); return r; }

__device__ __forceinline__ void cp_async16(void* sm, const void* gm) {
    unsigned a = (unsigned)__cvta_generic_to_shared(sm);
    asm volatile("cp.async.cg.shared.global [%0], [%1], 16;\n" :: "r"(a), "l"(gm));
}
__device__ __forceinline__ void cp_commit() { asm volatile("cp.async.commit_group;\n" ::: "memory"); }
__device__ __forceinline__ void cp_wait1()  { asm volatile("cp.async.wait_group 1;\n" ::: "memory"); }
__device__ __forceinline__ void cp_wait0()  { asm volatile("cp.async.wait_group 0;\n" ::: "memory"); }

// =============================== Kernel A: scan =================================
__global__ __launch_bounds__(32, 1)
void hmets_scan(const float* __restrict__ x,
                const float* __restrict__ par,
                float* __restrict__ out)
{
    __shared__ float sm[2 * TS * ROWF];   // 23040 B double buffered
    const int lane = threadIdx.x;
    const int g0   = blockIdx.x * 32;
    const int g    = g0 + lane;
    const bool active  = (g < GG);
    const bool fullblk = (g0 + 32 <= GG);

    // -------- per-cell physical parameters (last timestep row only) -----------------
    const float* pr = par + ((size_t)(TT - 1) * GG + (active ? g : (GG - 1))) * 20;
    float s[16];
#pragma unroll
    for (int i = 0; i < 16; i++) {
        float v = __ldg(pr + i);
        s[i] = 1.0f / (1.0f + expf(-v));
    }
    const float ddf_min = 20.0f * s[0];
    const float ddf_sum = ddf_min + 20.0f * s[1];
    const float Tbm     = -2.0f + 5.0f * s[2];
    const float Kcum    = 0.01f + 0.19f * s[3];
    const float fcmin   = 0.1f * s[4];
    const float fc_sum  = fcmin + 0.01f + 0.24f * s[5];
    const float Ccum    = 0.005f + 0.045f * s[6];
    const float Tbf     = -5.0f + 7.0f * s[7];
    const float Kf      = 5.0f * s[8];
    const float efe     = s[9];
    const float ETe     = 3.0f * s[10];
    const float cRun    = s[11];
    const float cV2P    = 1e-5f + (0.02f - 1e-5f) * s[12];
    const float cVad    = 0.1f * s[13];
    const float cPh     = 1e-5f + (0.01f - 1e-5f) * s[14];
    const float Vmax    = 0.001f + (500.0f - 0.001f) * s[15];
    const float invVmax = 1.0f / Vmax;

    // -------- forcing tile prefetch (cp.async, zero-padded) -------------------------
    auto prefetch = [&](int k) {
        float* dst = sm + (k & 1) * (TS * ROWF);
        int t0 = k * TS;
        if (fullblk) {
            for (int j = lane; j < TS * 24; j += 32) {       // 24 float4 per row
                int row = j / 24, c = j - row * 24;
                if (t0 + row < TT) {
                    const float* gp = x + (size_t)(t0 + row) * (GG * 3) + g0 * 3 + c * 4;
                    cp_async16(dst + row * ROWF + c * 4, gp);
                } else {
                    float4 z = {0.f, 0.f, 0.f, 0.f};
                    *(float4*)(dst + row * ROWF + c * 4) = z;
                }
            }
        } else {
            for (int j = lane; j < TS * ROWF; j += 32) {
                int row = j / ROWF, c = j - row * ROWF;
                int cell = g0 + c / 3;
                dst[row * ROWF + c] = (cell < GG && t0 + row < TT)
                    ? __ldg(x + (size_t)(t0 + row) * (GG * 3) + g0 * 3 + c) : 0.0f;
            }
        }
        cp_commit();
    };

    float S = 1e-5f, W = 1e-5f, C = 1e-5f, P = 1e-5f;
    float V = 0.5f * Vmax;

    float2* sp = g_scratch + g;   // advances by GG per step
    float*  op = out + g;

    prefetch(0);
    for (int k = 0; k < NT; k++) {
        const int t0 = k * TS;
        const int len = min(TS, TT - t0);
        if (k + 1 < NT) { prefetch(k + 1); cp_wait1(); }
        else            { cp_wait0(); }
        __syncwarp();
        const float* rb = sm + (k & 1) * (TS * ROWF) + lane * 3;

#pragma unroll 6
        for (int i = 0; i < len; i++) {
            float Pp = rb[i * ROWF + 0];
            float Tt = rb[i * ROWF + 1];
            float PE = rb[i * ROWF + 2];

            float rain = (Tt >= 0.0f) ? Pp : 0.0f;
            float snow = Pp - rain;

            // refreeze (MUFU path, off the state chain)
            float base   = fmaxf(Tbf - Tt, 1e-5f);
            float pot_fr = Kf * ex2a(efe * lg2a(base));
            float fr     = fminf(pot_fr, W);
            W -= fr;
            S += fr;

            // melt
            float ddf  = fminf(ddf_sum, ddf_min * fmaf(Kcum, C, 1.0f));
            float S1   = S + snow;
            float melt = fminf(fmaxf(ddf * (Tt - Tbm), 0.0f), S1);
            S = S1 - melt;
            C = (S > 1e-5f) ? (C + melt) : 0.0f;

            // water retention
            float wrf  = fmaxf(fc_sum * fmaf(-Ccum, C, 1.0f), fcmin);
            float wr   = wrf * S;
            float wtmp = W + melt + rain;
            float wa   = fmaxf(wtmp - wr, 0.0f);
            W = (wa > 0.0f) ? wr : wtmp;

            // vadose / phreatic
            float RET   = ETe * PE;
            float ratio = V * invVmax;
            float cr    = cRun * ratio;
            float ht0   = cr * wa;
            float infil = fmaxf(wa - ht0 - RET, 0.0f);
            float ht1   = cr * ratio * infil;
            float ht2   = cVad * V;
            float v2p   = cV2P * V;
            V = V + infil - ht1 - ht2 - v2p;
            float over = fmaxf(V - Vmax, 0.0f);
            V -= over;
            ht1 += over;
            P += v2p;
            float ht3 = cPh * P;
            P -= ht3;

            if (active) {
                float2 h; h.x = ht0; h.y = ht1;
                *sp = h;                 // STG.64, coalesced
                *op = ht2 + ht3;         // q_gw partial; conv kernel adds the rest
            }
            sp += GG; op += GG;
        }
        __syncwarp();
    }
}

// ============================ Kernel B: dual gamma-UH conv ======================
// grid (157, 14), block 32. Each thread: one cell, one 105-step t-slice.
__global__ __launch_bounds__(32, 8)
void hmets_conv(const float* __restrict__ par,
                float* __restrict__ out)
{
    const int lane = threadIdx.x;
    const int g    = blockIdx.x * 32 + lane;
    if (g >= GG) return;
    const int t0   = blockIdx.y * SLEN;

    // routing params (sigmoid of last row, cols 16..19)
    const float* pr = par + ((size_t)(TT - 1) * GG + g) * 20 + 16;
    float a1 = 0.3f  + (20.0f - 0.3f)  / (1.0f + expf(-__ldg(pr + 0)));
    float b1 = 0.01f + (5.0f  - 0.01f) / (1.0f + expf(-__ldg(pr + 1)));
    float a2 = 0.5f  + (13.0f - 0.5f)  / (1.0f + expf(-__ldg(pr + 2)));
    float b2 = 0.15f + (1.5f  - 0.15f) / (1.0f + expf(-__ldg(pr + 3)));

    unsigned long long uhp[CH];
    {
        float i1 = 1.0f / b1, i2 = 1.0f / b2;
        float w1[CH], w2[CH];
        float n1 = 0.f, n2 = 0.f;
#pragma unroll
        for (int l = 0; l < CH; l++) {
            float t  = (float)l + 0.5f;
            w1[l] = powf(t, a1 - 1.0f) * expf(-t * i1);
            w2[l] = powf(t, a2 - 1.0f) * expf(-t * i2);
            n1 += w1[l]; n2 += w2[l];
        }
        n1 = 1.0f / n1; n2 = 1.0f / n2;
#pragma unroll
        for (int l = 0; l < CH; l++) PACK2(uhp[l], w1[l] * n1, w2[l] * n2);
    }

    // ring preload: hpk[j] = h[t0 - 15 + j] for j = 1..14 (zero if t < 0)
    unsigned long long hpk[CH];
    hpk[0] = 0ull;
#pragma unroll
    for (int j = 1; j < CH; j++) {
        int t = t0 - CH + j;
        if (t >= 0) {
            float2 h = g_scratch[(size_t)t * GG + g];
            PACK2(hpk[j], h.x, h.y);
        } else hpk[j] = 0ull;
    }

    const float2* sp = g_scratch + (size_t)t0 * GG + g;
    float* op = out + (size_t)t0 * GG + g;

#pragma unroll 1
    for (int cb = 0; cb < SLEN / CH; cb++) {
        const int tb = t0 + cb * CH;
        if (tb >= TT) break;
#pragma unroll
        for (int u = 0; u < CH; u++) {
            if (tb + u >= TT) break;
            float2 h = sp[(size_t)(cb * CH + u) * GG];
            PACK2(hpk[u], h.x, h.y);
            unsigned long long qp = 0ull;
#pragma unroll
            for (int l = 0; l < CH; l++)
                FMA2(qp, uhp[l], hpk[(u - l + CH) % CH], qp);
            float qlo, qhi;
            UNPACK2(qlo, qhi, qp);
            op[(size_t)(cb * CH + u) * GG] += qlo + qhi;
        }
    }
}

extern "C" void kernel_launch(void* const* d_in, const int* in_sizes, int n_in,
                              void* d_out, int out_size)
{
    (void)in_sizes; (void)n_in; (void)out_size;
    const float* x   = (const float*)d_in[0];   // x_phy  [1460, 5000, 3]
    const float* par = (const float*)d_in[1];   // params [1460, 5000, 20]
    float* out = (float*)d_out;                 // Q      [1460, 5000]

    hmets_scan<<<(GG + 31) / 32, 32>>>(x, par, out);
    dim3 cg((GG + 31) / 32, NSL);
    hmets_conv<<<cg, 32>>>(par, out);
}

// round 6
// speedup vs baseline: 1.0282x; 1.0282x over previous
#include <cuda_runtime.h>
#include <math.h>

#define TT   1460
#define GG   5000
#define TS   30              // timesteps per smem tile (2 x 15-chunk)
#define NT   49              // ceil(1460/30)
#define ROWF 96              // 32 cells * 3 floats per timestep row
#define CH   15              // UH length = ring period

// ---- packed f32x2 + approx transcendental helpers -----------------------------
#define PACK2(d, lo, hi)   asm("mov.b64 %0, {%1, %2};" : "=l"(d) : "f"(lo), "f"(hi))
#define UNPACK2(lo, hi, d) asm("mov.b64 {%0, %1}, %2;" : "=f"(lo), "=f"(hi) : "l"(d))
#define FMA2(d, a, b, c)   asm("fma.rn.f32x2 %0, %1, %2, %3;" : "=l"(d) : "l"(a), "l"(b), "l"(c))

__device__ __forceinline__ float lg2a(float x) { float r; asm("lg2.approx.f32 %0, %1;" : "=f"(r) : "f"(x)); return r; }
__device__ __forceinline__ float ex2a(float x) { float r; asm("ex2.approx.f32 %0, %1;" : "=f"(r) : "f"(x)); return r; }

__device__ __forceinline__ void cp_async16(void* sm, const void* gm) {
    unsigned a = (unsigned)__cvta_generic_to_shared(sm);
    asm volatile("cp.async.cg.shared.global [%0], [%1], 16;\n" :: "r"(a), "l"(gm));
}
__device__ __forceinline__ void cp_commit() { asm volatile("cp.async.commit_group;\n" ::: "memory"); }
__device__ __forceinline__ void cp_wait1()  { asm volatile("cp.async.wait_group 1;\n" ::: "memory"); }
__device__ __forceinline__ void cp_wait0()  { asm volatile("cp.async.wait_group 0;\n" ::: "memory"); }

__global__ __launch_bounds__(32, 1)
void hmets_kernel(const float* __restrict__ x,
                  const float* __restrict__ par,
                  float* __restrict__ out)
{
    __shared__ float sm[2 * TS * ROWF];   // 23040 B double buffered
    const int lane = threadIdx.x;
    const int g0   = blockIdx.x * 32;
    const int g    = g0 + lane;
    const bool active  = (g < GG);
    const bool fullblk = (g0 + 32 <= GG);

    // -------- per-cell parameters (last timestep row only) --------------------------
    const float* pr = par + ((size_t)(TT - 1) * GG + (active ? g : (GG - 1))) * 20;
    float s[20];
#pragma unroll
    for (int i = 0; i < 20; i++) {
        float v = __ldg(pr + i);
        s[i] = 1.0f / (1.0f + expf(-v));
    }
    const float ddf_min = 20.0f * s[0];
    const float ddf_sum = ddf_min + 20.0f * s[1];
    const float Tbm     = -2.0f + 5.0f * s[2];
    const float Kcum    = 0.01f + 0.19f * s[3];
    const float fcmin   = 0.1f * s[4];
    const float fc_sum  = fcmin + 0.01f + 0.24f * s[5];
    const float Ccum    = 0.005f + 0.045f * s[6];
    const float Tbf     = -5.0f + 7.0f * s[7];
    const float Kf      = 5.0f * s[8];
    const float efe     = s[9];
    const float ETe     = 3.0f * s[10];
    const float cRun    = s[11];
    const float cV2P    = 1e-5f + (0.02f - 1e-5f) * s[12];
    const float cVad    = 0.1f * s[13];
    const float cPh     = 1e-5f + (0.01f - 1e-5f) * s[14];
    const float Vmax    = 0.001f + (500.0f - 0.001f) * s[15];
    const float invVmax = 1.0f / Vmax;
    // spine-shortening precomputes
    const float dmK  = ddf_min * Kcum;       // ddf = fma(dmK, C, ddf_min)
    const float fcC  = fc_sum * Ccum;        // wrf = fma(-fcC, C, fc_sum)
    const float cVb  = 1.0f - cVad - cV2P;   // V' = fma(cVb, V, infil) - ht1

    // -------- gamma UH weights, packed (uh1[l], uh2[l]) -----------------------------
    unsigned long long uhp[CH];
    {
        float a1 = 0.3f  + (20.0f - 0.3f)  * s[16];
        float b1 = 0.01f + (5.0f  - 0.01f) * s[17];
        float a2 = 0.5f  + (13.0f - 0.5f)  * s[18];
        float b2 = 0.15f + (1.5f  - 0.15f) * s[19];
        float i1 = 1.0f / b1, i2 = 1.0f / b2;
        float w1[CH], w2[CH];
        float n1 = 0.f, n2 = 0.f;
#pragma unroll
        for (int l = 0; l < CH; l++) {
            float t  = (float)l + 0.5f;
            float lt = __log2f(t);
            w1[l] = ex2a(fmaf(a1 - 1.0f, lt, -t * i1 * 1.44269504f));
            w2[l] = ex2a(fmaf(a2 - 1.0f, lt, -t * i2 * 1.44269504f));
            n1 += w1[l]; n2 += w2[l];
        }
        n1 = 1.0f / n1; n2 = 1.0f / n2;
#pragma unroll
        for (int l = 0; l < CH; l++) PACK2(uhp[l], w1[l] * n1, w2[l] * n2);
    }

    // -------- forcing tile prefetch (cp.async, zero-padded) -------------------------
    auto prefetch = [&](int k) {
        float* dst = sm + (k & 1) * (TS * ROWF);
        int t0 = k * TS;
        if (fullblk) {
            for (int j = lane; j < TS * 24; j += 32) {       // 24 float4 per row
                int row = j / 24, c = j - row * 24;
                if (t0 + row < TT) {
                    const float* gp = x + (size_t)(t0 + row) * (GG * 3) + g0 * 3 + c * 4;
                    cp_async16(dst + row * ROWF + c * 4, gp);
                } else {
                    float4 z = {0.f, 0.f, 0.f, 0.f};
                    *(float4*)(dst + row * ROWF + c * 4) = z;
                }
            }
        } else {
            for (int j = lane; j < TS * ROWF; j += 32) {
                int row = j / ROWF, c = j - row * ROWF;
                int cell = g0 + c / 3;
                dst[row * ROWF + c] = (cell < GG && t0 + row < TT)
                    ? __ldg(x + (size_t)(t0 + row) * (GG * 3) + g0 * 3 + c) : 0.0f;
            }
        }
        cp_commit();
    };

    // -------- state + conv ring -----------------------------------------------------
    float S = 1e-5f, W = 1e-5f, C = 1e-5f, P = 1e-5f;
    float V = 0.5f * Vmax;
    unsigned long long hpk[CH];
#pragma unroll
    for (int l = 0; l < CH; l++) hpk[l] = 0ull;

    float* op = out + g;

    prefetch(0);
    for (int k = 0; k < NT; k++) {
        const int t0 = k * TS;
        if (k + 1 < NT) { prefetch(k + 1); cp_wait1(); }
        else            { cp_wait0(); }
        __syncwarp();
        const float* sb = sm + (k & 1) * (TS * ROWF);

#pragma unroll 1
        for (int c2 = 0; c2 < 2; c2++) {
            const float* rb = sb + c2 * CH * ROWF + lane * 3;
            const int tb = t0 + c2 * CH;

            // ---- preamble: forcing-derived values, fully independent & pipelined ----
            float rainA[CH], snowA[CH], potfA[CH], dtpA[CH], retA[CH];
#pragma unroll
            for (int u = 0; u < CH; u++) {
                float Pp = rb[u * ROWF + 0];
                float Tt = rb[u * ROWF + 1];
                float PE = rb[u * ROWF + 2];
                float rain = (Tt >= 0.0f) ? Pp : 0.0f;
                rainA[u] = rain;
                snowA[u] = Pp - rain;
                float base = fmaxf(Tbf - Tt, 1e-5f);
                potfA[u]   = Kf * ex2a(efe * lg2a(base));
                dtpA[u]    = fmaxf(Tt - Tbm, 0.0f);
                retA[u]    = ETe * PE;
            }

            // ---- serial spine + fused conv ----
#pragma unroll
            for (int u = 0; u < CH; u++) {
                // snowpack
                float fr = fminf(potfA[u], W);
                W -= fr;
                S += fr;
                float ddf  = fminf(fmaf(dmK, C, ddf_min), ddf_sum);
                float S1   = S + snowA[u];
                float melt = fminf(ddf * dtpA[u], S1);
                S = S1 - melt;
                float Ct = C + melt;
                C = (S > 1e-5f) ? Ct : 0.0f;

                // retention
                float wrf  = fmaxf(fmaf(-fcC, C, fc_sum), fcmin);
                float wr   = wrf * S;
                float wtmp = (W + rainA[u]) + melt;
                float wa   = fmaxf(wtmp - wr, 0.0f);
                W = (wa > 0.0f) ? wr : wtmp;

                // vadose / phreatic
                float ratio = V * invVmax;
                float cr    = cRun * ratio;
                float cr2   = cr * ratio;
                float ht0   = cr * wa;
                float infil = fmaxf((wa - retA[u]) - ht0, 0.0f);
                float ht1   = cr2 * infil;
                float ht2   = cVad * V;
                float v2p   = cV2P * V;
                float Vb    = fmaf(cVb, V, infil);
                V = Vb - ht1;
                float over = fmaxf(V - Vmax, 0.0f);
                V -= over;
                ht1 += over;
                float Pp1 = P + v2p;
                float ht3 = cPh * Pp1;
                P = Pp1 - ht3;

                // 15-tap dual UH conv on register-renamed ring (off-spine)
                PACK2(hpk[u], ht0, ht1);
                unsigned long long qp = 0ull;
#pragma unroll
                for (int l = 0; l < CH; l++)
                    FMA2(qp, uhp[l], hpk[(u - l + CH) % CH], qp);
                float qlo, qhi;
                UNPACK2(qlo, qhi, qp);
                float q = (ht2 + ht3) + qlo + qhi;

                if (active && (tb + u) < TT) op[(size_t)(tb + u) * GG] = q;
            }
        }
        __syncwarp();
    }
}

extern "C" void kernel_launch(void* const* d_in, const int* in_sizes, int n_in,
                              void* d_out, int out_size)
{
    (void)in_sizes; (void)n_in; (void)out_size;
    const float* x   = (const float*)d_in[0];   // x_phy  [1460, 5000, 3]
    const float* par = (const float*)d_in[1];   // params [1460, 5000, 20]
    float* out = (float*)d_out;                 // Q      [1460, 5000]
    hmets_kernel<<<(GG + 31) / 32, 32>>>(x, par, out);
}